// round 9
// baseline (speedup 1.0000x reference)
#include <cuda_runtime.h>
#include <math.h>

#define SEQ  2048
#define HDIM 1024
#define GDIM 4096   // 4*H
#define NCLS 512
#define NB   128    // scan grid (<= SM count -> all resident)
#define NGRP 8      // warp-group arrival counters

// ---------------- scratch (static device globals) ------------------------------
__device__ float    g_gx[SEQ * GDIM];      // 32 MB: precomputed input gates
__device__ float    g_seqA[SEQ * HDIM];    // 8 MB: layer output ping
__device__ float    g_seqB[SEQ * HDIM];    // 8 MB: layer output pong
__device__ float    g_Wt[HDIM * GDIM];     // 16 MB: transposed weight (max size)
__device__ float    g_bzero[GDIM];         // stays zero (dummy 2nd bias)
__device__ unsigned g_cnt[NGRP * SEQ];     // cnt[w*SEQ + t]: 8KB group stride

// ---------------- fast, overflow-safe activations (validated r4/r8) -------------
__device__ __forceinline__ float fast_sigmoid(float x) {
    return __fdividef(1.f, 1.f + __expf(-x));
}
__device__ __forceinline__ float fast_tanh(float x) {
    float ax = fabsf(x);
    float e  = __expf(2.f * ax);
    float t  = 1.f - __fdividef(2.f, e + 1.f);
    return copysignf(t, x);
}

// ---------------- transpose: Wt[c][r] = W[r][c] ----------------------------------
__global__ void transpose_k(const float* __restrict__ W, float* __restrict__ Wt,
                            int R, int C) {
    __shared__ float tile[32][33];
    int c0 = blockIdx.x * 32, r0 = blockIdx.y * 32;
    int x = threadIdx.x, y = threadIdx.y;
#pragma unroll
    for (int j = 0; j < 32; j += 8)
        tile[y + j][x] = W[(size_t)(r0 + y + j) * C + (c0 + x)];
    __syncthreads();
#pragma unroll
    for (int j = 0; j < 32; j += 8)
        Wt[(size_t)(c0 + y + j) * R + (r0 + x)] = tile[x][y + j];
}

// ---------------- zero counters ----------------------------------------------------
__global__ void zero_k(unsigned* p, int n) {
    int i = blockIdx.x * 256 + threadIdx.x;
    if (i < n) p[i] = 0;
}

// ---------------- SGEMM (round-1/4 known-good) --------------------------------------
__global__ void __launch_bounds__(256) sgemm_bias_k(
    const float* __restrict__ A, const float* __restrict__ B,
    const float* __restrict__ b1, const float* __restrict__ b2,
    float* __restrict__ C, int M, int N, int K) {
    __shared__ float As[8][128];
    __shared__ float Bs[8][128];
    const int tid  = threadIdx.x;
    const int tx   = tid & 15;
    const int ty   = tid >> 4;
    const int brow = blockIdx.y * 128;
    const int bcol = blockIdx.x * 128;

    const int ar  = tid >> 1;
    const int ak  = (tid & 1) * 4;
    const int bkk = tid >> 5;
    const int bn  = (tid & 31) * 4;

    const float* Aptr = A + (size_t)(brow + ar) * K + ak;
    const float* Bptr = B + (size_t)bkk * N + bcol + bn;

    float acc[8][8];
#pragma unroll
    for (int i = 0; i < 8; i++)
#pragma unroll
        for (int j = 0; j < 8; j++) acc[i][j] = 0.f;

    for (int k0 = 0; k0 < K; k0 += 8) {
        float4 av = *(const float4*)(Aptr + k0);
        float4 bv = *(const float4*)(Bptr + (size_t)k0 * N);
        __syncthreads();
        As[ak + 0][ar] = av.x; As[ak + 1][ar] = av.y;
        As[ak + 2][ar] = av.z; As[ak + 3][ar] = av.w;
        *(float4*)&Bs[bkk][bn] = bv;
        __syncthreads();
#pragma unroll
        for (int kk = 0; kk < 8; kk++) {
            float a[8], b[8];
            *(float4*)&a[0] = *(const float4*)&As[kk][ty * 4];
            *(float4*)&a[4] = *(const float4*)&As[kk][64 + ty * 4];
            *(float4*)&b[0] = *(const float4*)&Bs[kk][tx * 4];
            *(float4*)&b[4] = *(const float4*)&Bs[kk][64 + tx * 4];
#pragma unroll
            for (int i = 0; i < 8; i++)
#pragma unroll
                for (int j = 0; j < 8; j++)
                    acc[i][j] = fmaf(a[i], b[j], acc[i][j]);
        }
    }
#pragma unroll
    for (int i = 0; i < 8; i++) {
        int row = brow + ((i < 4) ? (ty * 4 + i) : (64 + ty * 4 + (i - 4)));
#pragma unroll
        for (int jq = 0; jq < 2; jq++) {
            int col = bcol + ((jq == 0) ? (tx * 4) : (64 + tx * 4));
            float4 o;
            o.x = acc[i][jq * 4 + 0] + b1[col + 0] + b2[col + 0];
            o.y = acc[i][jq * 4 + 1] + b1[col + 1] + b2[col + 1];
            o.z = acc[i][jq * 4 + 2] + b1[col + 2] + b2[col + 2];
            o.w = acc[i][jq * 4 + 3] + b1[col + 3] + b2[col + 3];
            *(float4*)&C[(size_t)row * N + col] = o;
        }
    }
}

// ---------------- persistent LSTM scan (no-SMEM direct-global matvec) --------------
// grid = 128 CTAs x 256 threads. CTA b owns units [8b, 8b+8); warp w -> unit
// u = 8b + w, rows {u,H+u,2H+u,3H+u} of W_hh in registers, scalar fmaf matvec.
// Publish: lane 0 per warp stores h then red.release.gpu cnt[w][t] (same-thread
// ordering). Observe: warp 0 lanes 0-7 acquire-poll one group each, then one
// __syncthreads. Matvec reads h DIRECTLY from global: each step's 4KB address
// range is fresh (never L1-cached on this SM), so post-acquire plain LDG must
// miss L1 and fetch the released values from L2; 8 warps then share via L1.
__global__ void __launch_bounds__(256, 1) lstm_scan_k(
    const float* __restrict__ Whh, const float* __restrict__ gx,
    float* __restrict__ seqout, unsigned* __restrict__ cnt) {
    const int tid  = threadIdx.x;
    const int lane = tid & 31;
    const int w    = tid >> 5;
    const int u    = blockIdx.x * 8 + w;

    // persistent weights in registers (coalesced: lane-stride 16B)
    float4 wr[4][8];
#pragma unroll
    for (int g = 0; g < 4; g++) {
        const float* wp = Whh + (size_t)(g * HDIM + u) * HDIM + lane * 4;
#pragma unroll
        for (int c = 0; c < 8; c++) wr[g][c] = *(const float4*)(wp + c * 128);
    }

    float cst = 0.f;

    for (int t = 0; t < SEQ; t++) {
        // gx loads for this step (warp-broadcast, complete under the spin)
        const float* p = gx + (size_t)t * GDIM + u;
        float gi = __ldg(p);
        float gf = __ldg(p + HDIM);
        float gg = __ldg(p + 2 * HDIM);
        float go = __ldg(p + 3 * HDIM);

        float a0 = 0.f, a1 = 0.f, a2 = 0.f, a3 = 0.f;

        if (t > 0) {
            // observe step t-1: warp 0 lanes 0-7, one warp-group counter each
            if (w == 0) {
                if (lane < NGRP) {
                    const unsigned* cp = cnt + lane * SEQ + (t - 1);
                    unsigned v;
                    do {
                        asm volatile("ld.acquire.gpu.global.u32 %0, [%1];"
                                     : "=r"(v) : "l"(cp) : "memory");
                    } while (v < (unsigned)NB);
                }
                __syncwarp();
            }
            __syncthreads();   // propagate observation to all warps

            // direct-global matvec: front-batched LDG.128 (MLP=8), then FMAs
            const float4* hp = (const float4*)(seqout + (size_t)(t - 1) * HDIM);
            float4 hv[8];
#pragma unroll
            for (int c = 0; c < 8; c++) hv[c] = hp[c * 32 + lane];
#pragma unroll
            for (int c = 0; c < 8; c++) {
                a0 = fmaf(wr[0][c].x, hv[c].x, a0); a0 = fmaf(wr[0][c].y, hv[c].y, a0);
                a0 = fmaf(wr[0][c].z, hv[c].z, a0); a0 = fmaf(wr[0][c].w, hv[c].w, a0);
                a1 = fmaf(wr[1][c].x, hv[c].x, a1); a1 = fmaf(wr[1][c].y, hv[c].y, a1);
                a1 = fmaf(wr[1][c].z, hv[c].z, a1); a1 = fmaf(wr[1][c].w, hv[c].w, a1);
                a2 = fmaf(wr[2][c].x, hv[c].x, a2); a2 = fmaf(wr[2][c].y, hv[c].y, a2);
                a2 = fmaf(wr[2][c].z, hv[c].z, a2); a2 = fmaf(wr[2][c].w, hv[c].w, a2);
                a3 = fmaf(wr[3][c].x, hv[c].x, a3); a3 = fmaf(wr[3][c].y, hv[c].y, a3);
                a3 = fmaf(wr[3][c].z, hv[c].z, a3); a3 = fmaf(wr[3][c].w, hv[c].w, a3);
            }
#pragma unroll
            for (int s = 16; s > 0; s >>= 1) {
                a0 += __shfl_xor_sync(0xffffffffu, a0, s);
                a1 += __shfl_xor_sync(0xffffffffu, a1, s);
                a2 += __shfl_xor_sync(0xffffffffu, a2, s);
                a3 += __shfl_xor_sync(0xffffffffu, a3, s);
            }
        }
        // t == 0: h == 0 -> matvec contributes nothing (a* stay 0)

        // all lanes compute identical gates (no divergence, MUFU fast path)
        float iv = fast_sigmoid(a0 + gi);
        float fv = fast_sigmoid(a1 + gf);
        float gv = fast_tanh(a2 + gg);
        float ov = fast_sigmoid(a3 + go);
        cst = fmaf(fv, cst, iv * gv);
        float h = ov * fast_tanh(cst);

        // per-warp publish: store h then release THIS warp's group counter
        if (lane == 0) {
            seqout[(size_t)t * HDIM + u] = h;
            asm volatile("red.release.gpu.global.add.u32 [%0], 1;"
                         :: "l"(cnt + w * SEQ + t) : "memory");
        }
        // next step's __syncthreads (after warp0's poll) resynchronizes the CTA
    }
}

// ---------------- launch ----------------
extern "C" void kernel_launch(void* const* d_in, const int* in_sizes, int n_in,
                              void* d_out, int out_size) {
    const float* x      = (const float*)d_in[0];
    const float* Wih[3] = {(const float*)d_in[1], (const float*)d_in[5],  (const float*)d_in[9]};
    const float* Whh[3] = {(const float*)d_in[2], (const float*)d_in[6],  (const float*)d_in[10]};
    const float* bih[3] = {(const float*)d_in[3], (const float*)d_in[7],  (const float*)d_in[11]};
    const float* bhh[3] = {(const float*)d_in[4], (const float*)d_in[8],  (const float*)d_in[12]};
    const float* fcw    = (const float*)d_in[13];
    const float* fcb    = (const float*)d_in[14];
    float* out = (float*)d_out;

    float *gx, *seqA, *seqB, *Wt, *bz;
    unsigned* cnt;
    cudaGetSymbolAddress((void**)&gx,   g_gx);
    cudaGetSymbolAddress((void**)&seqA, g_seqA);
    cudaGetSymbolAddress((void**)&seqB, g_seqB);
    cudaGetSymbolAddress((void**)&Wt,   g_Wt);
    cudaGetSymbolAddress((void**)&bz,   g_bzero);
    cudaGetSymbolAddress((void**)&cnt,  g_cnt);

    const float* ins[3]  = {x, seqA, seqB};
    float*       outs[3] = {seqA, seqB, seqA};

    dim3 tb(32, 8);
    for (int l = 0; l < 3; l++) {
        transpose_k<<<dim3(HDIM / 32, GDIM / 32), tb>>>(Wih[l], Wt, GDIM, HDIM);
        sgemm_bias_k<<<dim3(GDIM / 128, SEQ / 128), 256>>>(
            ins[l], Wt, bih[l], bhh[l], gx, SEQ, GDIM, HDIM);
        zero_k<<<(NGRP * SEQ + 255) / 256, 256>>>(cnt, NGRP * SEQ);
        lstm_scan_k<<<NB, 256>>>(Whh[l], gx, outs[l], cnt);
    }
    // FC head
    transpose_k<<<dim3(HDIM / 32, NCLS / 32), tb>>>(fcw, Wt, NCLS, HDIM);
    sgemm_bias_k<<<dim3(NCLS / 128, SEQ / 128), 256>>>(
        seqA, Wt, fcb, bz, out, SEQ, NCLS, HDIM);
}

// round 10
// speedup vs baseline: 1.0123x; 1.0123x over previous
#include <cuda_runtime.h>
#include <math.h>

#define SEQ  2048
#define HDIM 1024
#define GDIM 4096   // 4*H
#define NCLS 512
#define NB   128    // scan grid (<= SM count -> all resident)
#define NGRP 8      // warp-group arrival counters

typedef unsigned long long ull;

// ---------------- scratch (static device globals) ------------------------------
__device__ float    g_gx[SEQ * GDIM];      // 32 MB: precomputed input gates
__device__ float    g_seqA[SEQ * HDIM];    // 8 MB: layer output ping
__device__ float    g_seqB[SEQ * HDIM];    // 8 MB: layer output pong
__device__ float    g_Wt[HDIM * GDIM];     // 16 MB: transposed weight (max size)
__device__ float    g_bzero[GDIM];         // stays zero (dummy 2nd bias)
__device__ unsigned g_cnt[NGRP * SEQ];     // cnt[w*SEQ + t]: 8KB group stride

// ---------------- packed f32x2 helpers (NO volatile: let ptxas schedule) --------
__device__ __forceinline__ ull pk(float lo, float hi) {
    ull r; asm("mov.b64 %0, {%1, %2};" : "=l"(r) : "f"(lo), "f"(hi)); return r;
}
__device__ __forceinline__ float2 up(ull v) {
    float2 r; asm("mov.b64 {%0, %1}, %2;" : "=f"(r.x), "=f"(r.y) : "l"(v)); return r;
}
__device__ __forceinline__ void fma2(ull& d, ull a, ull b) {
    asm("fma.rn.f32x2 %0, %1, %2, %0;" : "+l"(d) : "l"(a), "l"(b));
}

// ---------------- fast, overflow-safe activations (validated r4/r8) -------------
__device__ __forceinline__ float fast_sigmoid(float x) {
    return __fdividef(1.f, 1.f + __expf(-x));
}
__device__ __forceinline__ float fast_tanh(float x) {
    float ax = fabsf(x);
    float e  = __expf(2.f * ax);
    float t  = 1.f - __fdividef(2.f, e + 1.f);
    return copysignf(t, x);
}

// ---------------- transpose: Wt[c][r] = W[r][c] ----------------------------------
__global__ void transpose_k(const float* __restrict__ W, float* __restrict__ Wt,
                            int R, int C) {
    __shared__ float tile[32][33];
    int c0 = blockIdx.x * 32, r0 = blockIdx.y * 32;
    int x = threadIdx.x, y = threadIdx.y;
#pragma unroll
    for (int j = 0; j < 32; j += 8)
        tile[y + j][x] = W[(size_t)(r0 + y + j) * C + (c0 + x)];
    __syncthreads();
#pragma unroll
    for (int j = 0; j < 32; j += 8)
        Wt[(size_t)(c0 + y + j) * R + (r0 + x)] = tile[x][y + j];
}

// ---------------- zero counters ----------------------------------------------------
__global__ void zero_k(unsigned* p, int n) {
    int i = blockIdx.x * 256 + threadIdx.x;
    if (i < n) p[i] = 0;
}

// ---------------- SGEMM (round-1/4 known-good) --------------------------------------
__global__ void __launch_bounds__(256) sgemm_bias_k(
    const float* __restrict__ A, const float* __restrict__ B,
    const float* __restrict__ b1, const float* __restrict__ b2,
    float* __restrict__ C, int M, int N, int K) {
    __shared__ float As[8][128];
    __shared__ float Bs[8][128];
    const int tid  = threadIdx.x;
    const int tx   = tid & 15;
    const int ty   = tid >> 4;
    const int brow = blockIdx.y * 128;
    const int bcol = blockIdx.x * 128;

    const int ar  = tid >> 1;
    const int ak  = (tid & 1) * 4;
    const int bkk = tid >> 5;
    const int bn  = (tid & 31) * 4;

    const float* Aptr = A + (size_t)(brow + ar) * K + ak;
    const float* Bptr = B + (size_t)bkk * N + bcol + bn;

    float acc[8][8];
#pragma unroll
    for (int i = 0; i < 8; i++)
#pragma unroll
        for (int j = 0; j < 8; j++) acc[i][j] = 0.f;

    for (int k0 = 0; k0 < K; k0 += 8) {
        float4 av = *(const float4*)(Aptr + k0);
        float4 bv = *(const float4*)(Bptr + (size_t)k0 * N);
        __syncthreads();
        As[ak + 0][ar] = av.x; As[ak + 1][ar] = av.y;
        As[ak + 2][ar] = av.z; As[ak + 3][ar] = av.w;
        *(float4*)&Bs[bkk][bn] = bv;
        __syncthreads();
#pragma unroll
        for (int kk = 0; kk < 8; kk++) {
            float a[8], b[8];
            *(float4*)&a[0] = *(const float4*)&As[kk][ty * 4];
            *(float4*)&a[4] = *(const float4*)&As[kk][64 + ty * 4];
            *(float4*)&b[0] = *(const float4*)&Bs[kk][tx * 4];
            *(float4*)&b[4] = *(const float4*)&Bs[kk][64 + tx * 4];
#pragma unroll
            for (int i = 0; i < 8; i++)
#pragma unroll
                for (int j = 0; j < 8; j++)
                    acc[i][j] = fmaf(a[i], b[j], acc[i][j]);
        }
    }
#pragma unroll
    for (int i = 0; i < 8; i++) {
        int row = brow + ((i < 4) ? (ty * 4 + i) : (64 + ty * 4 + (i - 4)));
#pragma unroll
        for (int jq = 0; jq < 2; jq++) {
            int col = bcol + ((jq == 0) ? (tx * 4) : (64 + tx * 4));
            float4 o;
            o.x = acc[i][jq * 4 + 0] + b1[col + 0] + b2[col + 0];
            o.y = acc[i][jq * 4 + 1] + b1[col + 1] + b2[col + 1];
            o.z = acc[i][jq * 4 + 2] + b1[col + 2] + b2[col + 2];
            o.w = acc[i][jq * 4 + 3] + b1[col + 3] + b2[col + 3];
            *(float4*)&C[(size_t)row * N + col] = o;
        }
    }
}

// ---------------- persistent LSTM scan (r8 skeleton + packed f32x2 matvec) ---------
// grid = 128 CTAs x 256 threads. CTA b owns units [8b, 8b+8); warp w -> unit
// u = 8b + w, rows {u,H+u,2H+u,3H+u} of W_hh in registers as f32x2 pairs.
// Publish: lane 0 per warp stores h then red.release.gpu cnt[w][t]. Observe:
// warp 0 lanes 0-7 acquire-poll one group each, bar, stage h via SMEM (r8 path).
// Matvec: compiler-batched LDS.128 of h, pack halves (mov.b64), fma.rn.f32x2.
__global__ void __launch_bounds__(256, 1) lstm_scan_k(
    const float* __restrict__ Whh, const float* __restrict__ gx,
    float* __restrict__ seqout, unsigned* __restrict__ cnt) {
    __shared__ float4 sh[HDIM / 4];
    const int tid  = threadIdx.x;
    const int lane = tid & 31;
    const int w    = tid >> 5;
    const int u    = blockIdx.x * 8 + w;

    // persistent weights in registers, packed once as f32x2 pairs
    ull wp[4][16];
#pragma unroll
    for (int g = 0; g < 4; g++) {
        const float* wptr = Whh + (size_t)(g * HDIM + u) * HDIM + lane * 4;
#pragma unroll
        for (int c = 0; c < 8; c++) {
            float4 v = *(const float4*)(wptr + c * 128);
            wp[g][2 * c]     = pk(v.x, v.y);
            wp[g][2 * c + 1] = pk(v.z, v.w);
        }
    }

    float cst = 0.f;
    const float4* hsrc = 0;

    for (int t = 0; t < SEQ; t++) {
        // gx loads for this step (warp-broadcast, complete under the spin)
        const float* p = gx + (size_t)t * GDIM + u;
        float gi = __ldg(p);
        float gf = __ldg(p + HDIM);
        float gg = __ldg(p + 2 * HDIM);
        float go = __ldg(p + 3 * HDIM);

        if (t == 0) {
            sh[tid] = make_float4(0.f, 0.f, 0.f, 0.f);
            __syncthreads();
        } else {
            // observe step t-1: warp 0 lanes 0-7, one warp-group counter each
            if (w == 0) {
                if (lane < NGRP) {
                    const unsigned* cp = cnt + lane * SEQ + (t - 1);
                    unsigned v;
                    do {
                        asm volatile("ld.acquire.gpu.global.u32 %0, [%1];"
                                     : "=r"(v) : "l"(cp) : "memory");
                    } while (v < (unsigned)NB);
                }
                __syncwarp();
            }
            __syncthreads();                  // propagate observation; also ends
                                              // prior step's sh reads before write
            sh[tid] = __ldcg(hsrc + tid);     // stage h_{t-1} (4KB via L2)
            __syncthreads();
        }

        ull a0 = 0ull, a1 = 0ull, a2 = 0ull, a3 = 0ull;
#pragma unroll
        for (int c = 0; c < 8; c++) {
            float4 hv = sh[c * 32 + lane];    // batched LDS.128 (no volatile)
            ull h01 = pk(hv.x, hv.y);
            ull h23 = pk(hv.z, hv.w);
            fma2(a0, wp[0][2 * c], h01); fma2(a0, wp[0][2 * c + 1], h23);
            fma2(a1, wp[1][2 * c], h01); fma2(a1, wp[1][2 * c + 1], h23);
            fma2(a2, wp[2][2 * c], h01); fma2(a2, wp[2][2 * c + 1], h23);
            fma2(a3, wp[3][2 * c], h01); fma2(a3, wp[3][2 * c + 1], h23);
        }
        float2 p0 = up(a0), p1 = up(a1), p2 = up(a2), p3 = up(a3);
        float s0 = p0.x + p0.y, s1 = p1.x + p1.y;
        float s2 = p2.x + p2.y, s3 = p3.x + p3.y;
#pragma unroll
        for (int s = 16; s > 0; s >>= 1) {
            s0 += __shfl_xor_sync(0xffffffffu, s0, s);
            s1 += __shfl_xor_sync(0xffffffffu, s1, s);
            s2 += __shfl_xor_sync(0xffffffffu, s2, s);
            s3 += __shfl_xor_sync(0xffffffffu, s3, s);
        }
        // all lanes compute identical gates (no divergence, MUFU fast path)
        float iv = fast_sigmoid(s0 + gi);
        float fv = fast_sigmoid(s1 + gf);
        float gv = fast_tanh(s2 + gg);
        float ov = fast_sigmoid(s3 + go);
        cst = fmaf(fv, cst, iv * gv);
        float h = ov * fast_tanh(cst);

        // per-warp publish: store h then release THIS warp's group counter
        if (lane == 0) {
            seqout[(size_t)t * HDIM + u] = h;
            asm volatile("red.release.gpu.global.add.u32 [%0], 1;"
                         :: "l"(cnt + w * SEQ + t) : "memory");
        }
        hsrc = (const float4*)(seqout + (size_t)t * HDIM);
        // sh reuse protected by the two bars at the top of the next step
    }
}

// ---------------- launch ----------------
extern "C" void kernel_launch(void* const* d_in, const int* in_sizes, int n_in,
                              void* d_out, int out_size) {
    const float* x      = (const float*)d_in[0];
    const float* Wih[3] = {(const float*)d_in[1], (const float*)d_in[5],  (const float*)d_in[9]};
    const float* Whh[3] = {(const float*)d_in[2], (const float*)d_in[6],  (const float*)d_in[10]};
    const float* bih[3] = {(const float*)d_in[3], (const float*)d_in[7],  (const float*)d_in[11]};
    const float* bhh[3] = {(const float*)d_in[4], (const float*)d_in[8],  (const float*)d_in[12]};
    const float* fcw    = (const float*)d_in[13];
    const float* fcb    = (const float*)d_in[14];
    float* out = (float*)d_out;

    float *gx, *seqA, *seqB, *Wt, *bz;
    unsigned* cnt;
    cudaGetSymbolAddress((void**)&gx,   g_gx);
    cudaGetSymbolAddress((void**)&seqA, g_seqA);
    cudaGetSymbolAddress((void**)&seqB, g_seqB);
    cudaGetSymbolAddress((void**)&Wt,   g_Wt);
    cudaGetSymbolAddress((void**)&bz,   g_bzero);
    cudaGetSymbolAddress((void**)&cnt,  g_cnt);

    const float* ins[3]  = {x, seqA, seqB};
    float*       outs[3] = {seqA, seqB, seqA};

    dim3 tb(32, 8);
    for (int l = 0; l < 3; l++) {
        transpose_k<<<dim3(HDIM / 32, GDIM / 32), tb>>>(Wih[l], Wt, GDIM, HDIM);
        sgemm_bias_k<<<dim3(GDIM / 128, SEQ / 128), 256>>>(
            ins[l], Wt, bih[l], bhh[l], gx, SEQ, GDIM, HDIM);
        zero_k<<<(NGRP * SEQ + 255) / 256, 256>>>(cnt, NGRP * SEQ);
        lstm_scan_k<<<NB, 256>>>(Whh[l], gx, outs[l], cnt);
    }
    // FC head
    transpose_k<<<dim3(HDIM / 32, NCLS / 32), tb>>>(fcw, Wt, NCLS, HDIM);
    sgemm_bias_k<<<dim3(NCLS / 128, SEQ / 128), 256>>>(
        seqA, Wt, fcb, bz, out, SEQ, NCLS, HDIM);
}

// round 11
// speedup vs baseline: 1.0331x; 1.0206x over previous
#include <cuda_runtime.h>
#include <math.h>

#define SEQ  2048
#define HDIM 1024
#define GDIM 4096   // 4*H
#define NCLS 512
#define NB   128    // scan grid (<= SM count -> all resident)
#define NGRP 8      // warp-group arrival counters

// ---------------- scratch (static device globals) ------------------------------
__device__ float    g_gx[SEQ * GDIM];      // 32 MB: precomputed input gates
__device__ float    g_seqA[SEQ * HDIM];    // 8 MB: layer output ping
__device__ float    g_seqB[SEQ * HDIM];    // 8 MB: layer output pong
__device__ float    g_Wt[HDIM * GDIM];     // 16 MB: transposed weight (max size)
__device__ float    g_bzero[GDIM];         // stays zero (dummy 2nd bias)
__device__ unsigned g_cnt[NGRP * SEQ];     // cnt[w*SEQ + t]: 8KB group stride

// ---------------- fast, overflow-safe activations (validated r4/r8) -------------
__device__ __forceinline__ float fast_sigmoid(float x) {
    return __fdividef(1.f, 1.f + __expf(-x));
}
__device__ __forceinline__ float fast_tanh(float x) {
    float ax = fabsf(x);
    float e  = __expf(2.f * ax);
    float t  = 1.f - __fdividef(2.f, e + 1.f);
    return copysignf(t, x);
}

// ---------------- transpose: Wt[c][r] = W[r][c] ----------------------------------
__global__ void transpose_k(const float* __restrict__ W, float* __restrict__ Wt,
                            int R, int C) {
    __shared__ float tile[32][33];
    int c0 = blockIdx.x * 32, r0 = blockIdx.y * 32;
    int x = threadIdx.x, y = threadIdx.y;
#pragma unroll
    for (int j = 0; j < 32; j += 8)
        tile[y + j][x] = W[(size_t)(r0 + y + j) * C + (c0 + x)];
    __syncthreads();
#pragma unroll
    for (int j = 0; j < 32; j += 8)
        Wt[(size_t)(c0 + y + j) * R + (r0 + x)] = tile[x][y + j];
}

// ---------------- zero counters ----------------------------------------------------
__global__ void zero_k(unsigned* p, int n) {
    int i = blockIdx.x * 256 + threadIdx.x;
    if (i < n) p[i] = 0;
}

// ---------------- SGEMM: C = A[M,K] @ B[K,N] + b1 + b2 ------------------------------
// BM=BN=128, BK=16, 256 threads, 8x8 microtile. Double-buffered SMEM with
// register staging: ONE __syncthreads per K-slice (vs 2 per 8-slice before),
// global loads issued right after the bar and consumed 1024 FMAs later.
// 2 CTAs/SM (32KB smem, <=128 regs). FMA order per element unchanged (k asc).
__global__ void __launch_bounds__(256, 2) sgemm_bias_k(
    const float* __restrict__ A, const float* __restrict__ B,
    const float* __restrict__ b1, const float* __restrict__ b2,
    float* __restrict__ C, int M, int N, int K) {
    __shared__ float As[2][16][128];
    __shared__ float Bs[2][16][128];
    const int tid  = threadIdx.x;
    const int tx   = tid & 15;
    const int ty   = tid >> 4;
    const int brow = blockIdx.y * 128;
    const int bcol = blockIdx.x * 128;

    // A staging: thread -> (row, 8-wide k chunk)
    const int arow = tid >> 1;          // 0..127
    const int ak   = (tid & 1) * 8;     // 0 or 8
    // B staging: thread -> (k row, two float4 cols)
    const int bk   = tid >> 4;          // 0..15
    const int bn   = (tid & 15) * 4;    // 0..60

    const float* Aptr = A + (size_t)(brow + arow) * K + ak;
    const float* Bptr = B + (size_t)bk * N + bcol + bn;

    float acc[8][8];
#pragma unroll
    for (int i = 0; i < 8; i++)
#pragma unroll
        for (int j = 0; j < 8; j++) acc[i][j] = 0.f;

    // prologue: load tile 0 and stage into buffer 0
    float4 av0 = *(const float4*)(Aptr);
    float4 av1 = *(const float4*)(Aptr + 4);
    float4 bv0 = *(const float4*)(Bptr);
    float4 bv1 = *(const float4*)(Bptr + 64);
    As[0][ak + 0][arow] = av0.x; As[0][ak + 1][arow] = av0.y;
    As[0][ak + 2][arow] = av0.z; As[0][ak + 3][arow] = av0.w;
    As[0][ak + 4][arow] = av1.x; As[0][ak + 5][arow] = av1.y;
    As[0][ak + 6][arow] = av1.z; As[0][ak + 7][arow] = av1.w;
    *(float4*)&Bs[0][bk][bn]      = bv0;
    *(float4*)&Bs[0][bk][bn + 64] = bv1;

    int cur = 0;
    for (int k0 = 0; k0 < K; k0 += 16) {
        __syncthreads();                       // buf[cur] stores visible
        const bool more = (k0 + 16) < K;
        if (more) {                            // prefetch next tile into regs
            av0 = *(const float4*)(Aptr + k0 + 16);
            av1 = *(const float4*)(Aptr + k0 + 20);
            bv0 = *(const float4*)(Bptr + (size_t)(k0 + 16) * N);
            bv1 = *(const float4*)(Bptr + (size_t)(k0 + 16) * N + 64);
        }
#pragma unroll
        for (int kk = 0; kk < 16; kk++) {
            float a[8], b[8];
            *(float4*)&a[0] = *(const float4*)&As[cur][kk][ty * 4];
            *(float4*)&a[4] = *(const float4*)&As[cur][kk][64 + ty * 4];
            *(float4*)&b[0] = *(const float4*)&Bs[cur][kk][tx * 4];
            *(float4*)&b[4] = *(const float4*)&Bs[cur][kk][64 + tx * 4];
#pragma unroll
            for (int i = 0; i < 8; i++)
#pragma unroll
                for (int j = 0; j < 8; j++)
                    acc[i][j] = fmaf(a[i], b[j], acc[i][j]);
        }
        if (more) {                            // stage regs into buf[cur^1]
            const int nxt = cur ^ 1;
            As[nxt][ak + 0][arow] = av0.x; As[nxt][ak + 1][arow] = av0.y;
            As[nxt][ak + 2][arow] = av0.z; As[nxt][ak + 3][arow] = av0.w;
            As[nxt][ak + 4][arow] = av1.x; As[nxt][ak + 5][arow] = av1.y;
            As[nxt][ak + 6][arow] = av1.z; As[nxt][ak + 7][arow] = av1.w;
            *(float4*)&Bs[nxt][bk][bn]      = bv0;
            *(float4*)&Bs[nxt][bk][bn + 64] = bv1;
            cur = nxt;
        }
    }
#pragma unroll
    for (int i = 0; i < 8; i++) {
        int row = brow + ((i < 4) ? (ty * 4 + i) : (64 + ty * 4 + (i - 4)));
#pragma unroll
        for (int jq = 0; jq < 2; jq++) {
            int col = bcol + ((jq == 0) ? (tx * 4) : (64 + tx * 4));
            float4 o;
            o.x = acc[i][jq * 4 + 0] + b1[col + 0] + b2[col + 0];
            o.y = acc[i][jq * 4 + 1] + b1[col + 1] + b2[col + 1];
            o.z = acc[i][jq * 4 + 2] + b1[col + 2] + b2[col + 2];
            o.w = acc[i][jq * 4 + 3] + b1[col + 3] + b2[col + 3];
            *(float4*)&C[(size_t)row * N + col] = o;
        }
    }
}

// ---------------- persistent LSTM scan (r8 champion, byte-identical) ---------------
__global__ void __launch_bounds__(256, 1) lstm_scan_k(
    const float* __restrict__ Whh, const float* __restrict__ gx,
    float* __restrict__ seqout, unsigned* __restrict__ cnt) {
    __shared__ float4 sh[HDIM / 4];
    const int tid  = threadIdx.x;
    const int lane = tid & 31;
    const int w    = tid >> 5;
    const int u    = blockIdx.x * 8 + w;

    // persistent weights in registers (coalesced: lane-stride 16B)
    float4 wr[4][8];
#pragma unroll
    for (int g = 0; g < 4; g++) {
        const float* wp = Whh + (size_t)(g * HDIM + u) * HDIM + lane * 4;
#pragma unroll
        for (int c = 0; c < 8; c++) wr[g][c] = *(const float4*)(wp + c * 128);
    }

    float cst = 0.f;
    const float4* hsrc = 0;

    for (int t = 0; t < SEQ; t++) {
        // gx loads for this step (warp-broadcast, complete under the spin)
        const float* p = gx + (size_t)t * GDIM + u;
        float gi = __ldg(p);
        float gf = __ldg(p + HDIM);
        float gg = __ldg(p + 2 * HDIM);
        float go = __ldg(p + 3 * HDIM);

        if (t == 0) {
            sh[tid] = make_float4(0.f, 0.f, 0.f, 0.f);
            __syncthreads();
        } else {
            // observe step t-1: warp 0 lanes 0-7, one warp-group counter each
            if (w == 0) {
                if (lane < NGRP) {
                    const unsigned* cp = cnt + lane * SEQ + (t - 1);
                    unsigned v;
                    do {
                        asm volatile("ld.acquire.gpu.global.u32 %0, [%1];"
                                     : "=r"(v) : "l"(cp) : "memory");
                    } while (v < (unsigned)NB);
                }
                __syncwarp();
            }
            __syncthreads();                  // propagate observation; also ends
                                              // prior step's sh reads before write
            sh[tid] = __ldcg(hsrc + tid);     // stage h_{t-1} (4KB via L2)
            __syncthreads();
        }

        float a0 = 0.f, a1 = 0.f, a2 = 0.f, a3 = 0.f;
#pragma unroll
        for (int c = 0; c < 8; c++) {
            float4 hv = sh[c * 32 + lane];
            a0 = fmaf(wr[0][c].x, hv.x, a0); a0 = fmaf(wr[0][c].y, hv.y, a0);
            a0 = fmaf(wr[0][c].z, hv.z, a0); a0 = fmaf(wr[0][c].w, hv.w, a0);
            a1 = fmaf(wr[1][c].x, hv.x, a1); a1 = fmaf(wr[1][c].y, hv.y, a1);
            a1 = fmaf(wr[1][c].z, hv.z, a1); a1 = fmaf(wr[1][c].w, hv.w, a1);
            a2 = fmaf(wr[2][c].x, hv.x, a2); a2 = fmaf(wr[2][c].y, hv.y, a2);
            a2 = fmaf(wr[2][c].z, hv.z, a2); a2 = fmaf(wr[2][c].w, hv.w, a2);
            a3 = fmaf(wr[3][c].x, hv.x, a3); a3 = fmaf(wr[3][c].y, hv.y, a3);
            a3 = fmaf(wr[3][c].z, hv.z, a3); a3 = fmaf(wr[3][c].w, hv.w, a3);
        }
#pragma unroll
        for (int s = 16; s > 0; s >>= 1) {
            a0 += __shfl_xor_sync(0xffffffffu, a0, s);
            a1 += __shfl_xor_sync(0xffffffffu, a1, s);
            a2 += __shfl_xor_sync(0xffffffffu, a2, s);
            a3 += __shfl_xor_sync(0xffffffffu, a3, s);
        }
        // all lanes compute identical gates (no divergence, MUFU fast path)
        float iv = fast_sigmoid(a0 + gi);
        float fv = fast_sigmoid(a1 + gf);
        float gv = fast_tanh(a2 + gg);
        float ov = fast_sigmoid(a3 + go);
        cst = fmaf(fv, cst, iv * gv);
        float h = ov * fast_tanh(cst);

        // per-warp publish: store h then release THIS warp's group counter
        if (lane == 0) {
            seqout[(size_t)t * HDIM + u] = h;
            asm volatile("red.release.gpu.global.add.u32 [%0], 1;"
                         :: "l"(cnt + w * SEQ + t) : "memory");
        }
        hsrc = (const float4*)(seqout + (size_t)t * HDIM);
        // sh reuse protected by the two bars at the top of the next step
    }
}

// ---------------- launch ----------------
extern "C" void kernel_launch(void* const* d_in, const int* in_sizes, int n_in,
                              void* d_out, int out_size) {
    const float* x      = (const float*)d_in[0];
    const float* Wih[3] = {(const float*)d_in[1], (const float*)d_in[5],  (const float*)d_in[9]};
    const float* Whh[3] = {(const float*)d_in[2], (const float*)d_in[6],  (const float*)d_in[10]};
    const float* bih[3] = {(const float*)d_in[3], (const float*)d_in[7],  (const float*)d_in[11]};
    const float* bhh[3] = {(const float*)d_in[4], (const float*)d_in[8],  (const float*)d_in[12]};
    const float* fcw    = (const float*)d_in[13];
    const float* fcb    = (const float*)d_in[14];
    float* out = (float*)d_out;

    float *gx, *seqA, *seqB, *Wt, *bz;
    unsigned* cnt;
    cudaGetSymbolAddress((void**)&gx,   g_gx);
    cudaGetSymbolAddress((void**)&seqA, g_seqA);
    cudaGetSymbolAddress((void**)&seqB, g_seqB);
    cudaGetSymbolAddress((void**)&Wt,   g_Wt);
    cudaGetSymbolAddress((void**)&bz,   g_bzero);
    cudaGetSymbolAddress((void**)&cnt,  g_cnt);

    const float* ins[3]  = {x, seqA, seqB};
    float*       outs[3] = {seqA, seqB, seqA};

    dim3 tb(32, 8);
    for (int l = 0; l < 3; l++) {
        transpose_k<<<dim3(HDIM / 32, GDIM / 32), tb>>>(Wih[l], Wt, GDIM, HDIM);
        sgemm_bias_k<<<dim3(GDIM / 128, SEQ / 128), 256>>>(
            ins[l], Wt, bih[l], bhh[l], gx, SEQ, GDIM, HDIM);
        zero_k<<<(NGRP * SEQ + 255) / 256, 256>>>(cnt, NGRP * SEQ);
        lstm_scan_k<<<NB, 256>>>(Whh[l], gx, outs[l], cnt);
    }
    // FC head
    transpose_k<<<dim3(HDIM / 32, NCLS / 32), tb>>>(fcw, Wt, NCLS, HDIM);
    sgemm_bias_k<<<dim3(NCLS / 128, SEQ / 128), 256>>>(
        seqA, Wt, fcb, bz, out, SEQ, NCLS, HDIM);
}

// round 12
// speedup vs baseline: 1.0408x; 1.0074x over previous
#include <cuda_runtime.h>
#include <math.h>

#define SEQ  2048
#define HDIM 1024
#define GDIM 4096   // 4*H
#define NCLS 512
#define NB   128    // scan grid (<= SM count -> all resident)
#define NGRP 8      // warp-group arrival counters

typedef unsigned long long ull;

// ---------------- scratch (static device globals) ------------------------------
__device__ float    g_gx[SEQ * GDIM];      // 32 MB: precomputed input gates
__device__ float    g_seqA[SEQ * HDIM];    // 8 MB: layer output ping
__device__ float    g_seqB[SEQ * HDIM];    // 8 MB: layer output pong
__device__ float    g_Wt[HDIM * GDIM];     // 16 MB: transposed weight (max size)
__device__ float    g_bzero[GDIM];         // stays zero (dummy 2nd bias)
__device__ unsigned g_cnt[NGRP * SEQ];     // cnt[w*SEQ + t]: 8KB group stride

// ---------------- packed f32x2 helpers (NO volatile: let ptxas schedule) --------
__device__ __forceinline__ ull pk(float lo, float hi) {
    ull r; asm("mov.b64 %0, {%1, %2};" : "=l"(r) : "f"(lo), "f"(hi)); return r;
}
__device__ __forceinline__ float2 up(ull v) {
    float2 r; asm("mov.b64 {%0, %1}, %2;" : "=f"(r.x), "=f"(r.y) : "l"(v)); return r;
}
__device__ __forceinline__ void fma2(ull& d, ull a, ull b) {
    asm("fma.rn.f32x2 %0, %1, %2, %0;" : "+l"(d) : "l"(a), "l"(b));
}

// ---------------- fast, overflow-safe activations (validated r4/r8) -------------
__device__ __forceinline__ float fast_sigmoid(float x) {
    return __fdividef(1.f, 1.f + __expf(-x));
}
__device__ __forceinline__ float fast_tanh(float x) {
    float ax = fabsf(x);
    float e  = __expf(2.f * ax);
    float t  = 1.f - __fdividef(2.f, e + 1.f);
    return copysignf(t, x);
}

// ---------------- transpose: Wt[c][r] = W[r][c] ----------------------------------
__global__ void transpose_k(const float* __restrict__ W, float* __restrict__ Wt,
                            int R, int C) {
    __shared__ float tile[32][33];
    int c0 = blockIdx.x * 32, r0 = blockIdx.y * 32;
    int x = threadIdx.x, y = threadIdx.y;
#pragma unroll
    for (int j = 0; j < 32; j += 8)
        tile[y + j][x] = W[(size_t)(r0 + y + j) * C + (c0 + x)];
    __syncthreads();
#pragma unroll
    for (int j = 0; j < 32; j += 8)
        Wt[(size_t)(c0 + y + j) * R + (r0 + x)] = tile[x][y + j];
}

// ---------------- zero counters ----------------------------------------------------
__global__ void zero_k(unsigned* p, int n) {
    int i = blockIdx.x * 256 + threadIdx.x;
    if (i < n) p[i] = 0;
}

// ---------------- SGEMM: C = A[M,K] @ B[K,N] + b1 + b2 ------------------------------
// BM=BN=128, BK=16, 256 threads, 8x8 microtile, double-buffered SMEM (r11).
// NEW: inner product uses fma.rn.f32x2 packed over the j (column) dimension:
// halves FFMA issue in the issue-bound inner loop. Each acc element keeps its
// own k-ascending IEEE-FMA chain -> bitwise-identical results to the scalar path.
__global__ void __launch_bounds__(256, 2) sgemm_bias_k(
    const float* __restrict__ A, const float* __restrict__ B,
    const float* __restrict__ b1, const float* __restrict__ b2,
    float* __restrict__ C, int M, int N, int K) {
    __shared__ float As[2][16][128];
    __shared__ float Bs[2][16][128];
    const int tid  = threadIdx.x;
    const int tx   = tid & 15;
    const int ty   = tid >> 4;
    const int brow = blockIdx.y * 128;
    const int bcol = blockIdx.x * 128;

    const int arow = tid >> 1;          // 0..127
    const int ak   = (tid & 1) * 8;     // 0 or 8
    const int bk   = tid >> 4;          // 0..15
    const int bn   = (tid & 15) * 4;    // 0..60

    const float* Aptr = A + (size_t)(brow + arow) * K + ak;
    const float* Bptr = B + (size_t)bk * N + bcol + bn;

    ull acc2[8][4];
#pragma unroll
    for (int i = 0; i < 8; i++)
#pragma unroll
        for (int j = 0; j < 4; j++) acc2[i][j] = 0ull;

    // prologue: load tile 0 and stage into buffer 0
    float4 av0 = *(const float4*)(Aptr);
    float4 av1 = *(const float4*)(Aptr + 4);
    float4 bv0 = *(const float4*)(Bptr);
    float4 bv1 = *(const float4*)(Bptr + 64);
    As[0][ak + 0][arow] = av0.x; As[0][ak + 1][arow] = av0.y;
    As[0][ak + 2][arow] = av0.z; As[0][ak + 3][arow] = av0.w;
    As[0][ak + 4][arow] = av1.x; As[0][ak + 5][arow] = av1.y;
    As[0][ak + 6][arow] = av1.z; As[0][ak + 7][arow] = av1.w;
    *(float4*)&Bs[0][bk][bn]      = bv0;
    *(float4*)&Bs[0][bk][bn + 64] = bv1;

    int cur = 0;
    for (int k0 = 0; k0 < K; k0 += 16) {
        __syncthreads();                       // buf[cur] stores visible
        const bool more = (k0 + 16) < K;
        if (more) {                            // prefetch next tile into regs
            av0 = *(const float4*)(Aptr + k0 + 16);
            av1 = *(const float4*)(Aptr + k0 + 20);
            bv0 = *(const float4*)(Bptr + (size_t)(k0 + 16) * N);
            bv1 = *(const float4*)(Bptr + (size_t)(k0 + 16) * N + 64);
        }
#pragma unroll
        for (int kk = 0; kk < 16; kk++) {
            float a[8];
            *(float4*)&a[0] = *(const float4*)&As[cur][kk][ty * 4];
            *(float4*)&a[4] = *(const float4*)&As[cur][kk][64 + ty * 4];
            float4 bq0 = *(const float4*)&Bs[cur][kk][tx * 4];
            float4 bq1 = *(const float4*)&Bs[cur][kk][64 + tx * 4];
            ull b01 = pk(bq0.x, bq0.y);
            ull b23 = pk(bq0.z, bq0.w);
            ull b45 = pk(bq1.x, bq1.y);
            ull b67 = pk(bq1.z, bq1.w);
#pragma unroll
            for (int i = 0; i < 8; i++) {
                ull sa = pk(a[i], a[i]);
                fma2(acc2[i][0], sa, b01);
                fma2(acc2[i][1], sa, b23);
                fma2(acc2[i][2], sa, b45);
                fma2(acc2[i][3], sa, b67);
            }
        }
        if (more) {                            // stage regs into buf[cur^1]
            const int nxt = cur ^ 1;
            As[nxt][ak + 0][arow] = av0.x; As[nxt][ak + 1][arow] = av0.y;
            As[nxt][ak + 2][arow] = av0.z; As[nxt][ak + 3][arow] = av0.w;
            As[nxt][ak + 4][arow] = av1.x; As[nxt][ak + 5][arow] = av1.y;
            As[nxt][ak + 6][arow] = av1.z; As[nxt][ak + 7][arow] = av1.w;
            *(float4*)&Bs[nxt][bk][bn]      = bv0;
            *(float4*)&Bs[nxt][bk][bn + 64] = bv1;
            cur = nxt;
        }
    }
#pragma unroll
    for (int i = 0; i < 8; i++) {
        int row = brow + ((i < 4) ? (ty * 4 + i) : (64 + ty * 4 + (i - 4)));
#pragma unroll
        for (int jq = 0; jq < 2; jq++) {
            int col = bcol + ((jq == 0) ? (tx * 4) : (64 + tx * 4));
            float2 lo = up(acc2[i][jq * 2 + 0]);
            float2 hi = up(acc2[i][jq * 2 + 1]);
            float4 o;
            o.x = lo.x + b1[col + 0] + b2[col + 0];
            o.y = lo.y + b1[col + 1] + b2[col + 1];
            o.z = hi.x + b1[col + 2] + b2[col + 2];
            o.w = hi.y + b1[col + 3] + b2[col + 3];
            *(float4*)&C[(size_t)row * N + col] = o;
        }
    }
}

// ---------------- persistent LSTM scan (r8 champion, byte-identical) ---------------
__global__ void __launch_bounds__(256, 1) lstm_scan_k(
    const float* __restrict__ Whh, const float* __restrict__ gx,
    float* __restrict__ seqout, unsigned* __restrict__ cnt) {
    __shared__ float4 sh[HDIM / 4];
    const int tid  = threadIdx.x;
    const int lane = tid & 31;
    const int w    = tid >> 5;
    const int u    = blockIdx.x * 8 + w;

    // persistent weights in registers (coalesced: lane-stride 16B)
    float4 wr[4][8];
#pragma unroll
    for (int g = 0; g < 4; g++) {
        const float* wp = Whh + (size_t)(g * HDIM + u) * HDIM + lane * 4;
#pragma unroll
        for (int c = 0; c < 8; c++) wr[g][c] = *(const float4*)(wp + c * 128);
    }

    float cst = 0.f;
    const float4* hsrc = 0;

    for (int t = 0; t < SEQ; t++) {
        // gx loads for this step (warp-broadcast, complete under the spin)
        const float* p = gx + (size_t)t * GDIM + u;
        float gi = __ldg(p);
        float gf = __ldg(p + HDIM);
        float gg = __ldg(p + 2 * HDIM);
        float go = __ldg(p + 3 * HDIM);

        if (t == 0) {
            sh[tid] = make_float4(0.f, 0.f, 0.f, 0.f);
            __syncthreads();
        } else {
            // observe step t-1: warp 0 lanes 0-7, one warp-group counter each
            if (w == 0) {
                if (lane < NGRP) {
                    const unsigned* cp = cnt + lane * SEQ + (t - 1);
                    unsigned v;
                    do {
                        asm volatile("ld.acquire.gpu.global.u32 %0, [%1];"
                                     : "=r"(v) : "l"(cp) : "memory");
                    } while (v < (unsigned)NB);
                }
                __syncwarp();
            }
            __syncthreads();                  // propagate observation; also ends
                                              // prior step's sh reads before write
            sh[tid] = __ldcg(hsrc + tid);     // stage h_{t-1} (4KB via L2)
            __syncthreads();
        }

        float a0 = 0.f, a1 = 0.f, a2 = 0.f, a3 = 0.f;
#pragma unroll
        for (int c = 0; c < 8; c++) {
            float4 hv = sh[c * 32 + lane];
            a0 = fmaf(wr[0][c].x, hv.x, a0); a0 = fmaf(wr[0][c].y, hv.y, a0);
            a0 = fmaf(wr[0][c].z, hv.z, a0); a0 = fmaf(wr[0][c].w, hv.w, a0);
            a1 = fmaf(wr[1][c].x, hv.x, a1); a1 = fmaf(wr[1][c].y, hv.y, a1);
            a1 = fmaf(wr[1][c].z, hv.z, a1); a1 = fmaf(wr[1][c].w, hv.w, a1);
            a2 = fmaf(wr[2][c].x, hv.x, a2); a2 = fmaf(wr[2][c].y, hv.y, a2);
            a2 = fmaf(wr[2][c].z, hv.z, a2); a2 = fmaf(wr[2][c].w, hv.w, a2);
            a3 = fmaf(wr[3][c].x, hv.x, a3); a3 = fmaf(wr[3][c].y, hv.y, a3);
            a3 = fmaf(wr[3][c].z, hv.z, a3); a3 = fmaf(wr[3][c].w, hv.w, a3);
        }
#pragma unroll
        for (int s = 16; s > 0; s >>= 1) {
            a0 += __shfl_xor_sync(0xffffffffu, a0, s);
            a1 += __shfl_xor_sync(0xffffffffu, a1, s);
            a2 += __shfl_xor_sync(0xffffffffu, a2, s);
            a3 += __shfl_xor_sync(0xffffffffu, a3, s);
        }
        // all lanes compute identical gates (no divergence, MUFU fast path)
        float iv = fast_sigmoid(a0 + gi);
        float fv = fast_sigmoid(a1 + gf);
        float gv = fast_tanh(a2 + gg);
        float ov = fast_sigmoid(a3 + go);
        cst = fmaf(fv, cst, iv * gv);
        float h = ov * fast_tanh(cst);

        // per-warp publish: store h then release THIS warp's group counter
        if (lane == 0) {
            seqout[(size_t)t * HDIM + u] = h;
            asm volatile("red.release.gpu.global.add.u32 [%0], 1;"
                         :: "l"(cnt + w * SEQ + t) : "memory");
        }
        hsrc = (const float4*)(seqout + (size_t)t * HDIM);
        // sh reuse protected by the two bars at the top of the next step
    }
}

// ---------------- launch ----------------
extern "C" void kernel_launch(void* const* d_in, const int* in_sizes, int n_in,
                              void* d_out, int out_size) {
    const float* x      = (const float*)d_in[0];
    const float* Wih[3] = {(const float*)d_in[1], (const float*)d_in[5],  (const float*)d_in[9]};
    const float* Whh[3] = {(const float*)d_in[2], (const float*)d_in[6],  (const float*)d_in[10]};
    const float* bih[3] = {(const float*)d_in[3], (const float*)d_in[7],  (const float*)d_in[11]};
    const float* bhh[3] = {(const float*)d_in[4], (const float*)d_in[8],  (const float*)d_in[12]};
    const float* fcw    = (const float*)d_in[13];
    const float* fcb    = (const float*)d_in[14];
    float* out = (float*)d_out;

    float *gx, *seqA, *seqB, *Wt, *bz;
    unsigned* cnt;
    cudaGetSymbolAddress((void**)&gx,   g_gx);
    cudaGetSymbolAddress((void**)&seqA, g_seqA);
    cudaGetSymbolAddress((void**)&seqB, g_seqB);
    cudaGetSymbolAddress((void**)&Wt,   g_Wt);
    cudaGetSymbolAddress((void**)&bz,   g_bzero);
    cudaGetSymbolAddress((void**)&cnt,  g_cnt);

    const float* ins[3]  = {x, seqA, seqB};
    float*       outs[3] = {seqA, seqB, seqA};

    dim3 tb(32, 8);
    for (int l = 0; l < 3; l++) {
        transpose_k<<<dim3(HDIM / 32, GDIM / 32), tb>>>(Wih[l], Wt, GDIM, HDIM);
        sgemm_bias_k<<<dim3(GDIM / 128, SEQ / 128), 256>>>(
            ins[l], Wt, bih[l], bhh[l], gx, SEQ, GDIM, HDIM);
        zero_k<<<(NGRP * SEQ + 255) / 256, 256>>>(cnt, NGRP * SEQ);
        lstm_scan_k<<<NB, 256>>>(Whh[l], gx, outs[l], cnt);
    }
    // FC head
    transpose_k<<<dim3(HDIM / 32, NCLS / 32), tb>>>(fcw, Wt, NCLS, HDIM);
    sgemm_bias_k<<<dim3(NCLS / 128, SEQ / 128), 256>>>(
        seqA, Wt, fcb, bz, out, SEQ, NCLS, HDIM);
}